// round 14
// baseline (speedup 1.0000x reference)
#include <cuda_runtime.h>
#include <cuda_bf16.h>
#include <cuda_fp16.h>
#include <stdint.h>

// LocalitySelfAttention: B=8, N=2304 (48x48), C=512, H=8, D=64.
// All-fp16 tensor pipeline (fp32 accumulate).
// Bias+temp+shift folded into augmented QK^T (D 64->72, aug via m16n8k8).
// ex2.approx.f16x2 softmax fused into the QK t-loop (low register lifetime),
// row-sums via ones-MMA. Single-barrier pipelines. Flash: 2 CTAs/SM.

constexpr int BB = 8;
constexpr int NN = 2304;
constexpr int CC = 512;
constexpr int HH = 8;
constexpr int DD = 64;
constexpr int DQ = 72;
constexpr int GG = 48;
constexpr int M_TOT = BB * NN;
constexpr size_t SX  = (size_t)M_TOT * CC;
constexpr size_t SQK = (size_t)BB * HH * NN * DQ;
constexpr size_t SQW = (size_t)1536 * 512;
constexpr size_t SPW = (size_t)512 * 512;
constexpr float LOG2E = 1.4426950408889634f;
constexpr float M0 = 8.0f;

__device__ __half g_xf[SX];
__device__ __half g_wqf[SQW];
__device__ __half g_wpf[SPW];
__device__ __half g_qf[SQK];         // [bh][n][72]
__device__ __half g_kf[SQK];         // [bh][n][72]
__device__ __half g_vtf[SX];         // [bh][d][n]
__device__ __half g_atf[SX];         // [b][n][C]

__device__ __forceinline__ uint32_t pack2h(__half a, __half b) {
    __half2 t; t.x = a; t.y = b;
    return *reinterpret_cast<uint32_t*>(&t);
}
__device__ __forceinline__ void mma16816h(float* c, const uint32_t* a, const uint32_t* b) {
    asm volatile(
        "mma.sync.aligned.m16n8k16.row.col.f32.f16.f16.f32 "
        "{%0,%1,%2,%3}, {%4,%5,%6,%7}, {%8,%9}, {%0,%1,%2,%3};"
        : "+f"(c[0]), "+f"(c[1]), "+f"(c[2]), "+f"(c[3])
        : "r"(a[0]), "r"(a[1]), "r"(a[2]), "r"(a[3]), "r"(b[0]), "r"(b[1]));
}
__device__ __forceinline__ void mma16808h(float* c, const uint32_t* a, uint32_t b) {
    asm volatile(
        "mma.sync.aligned.m16n8k8.row.col.f32.f16.f16.f32 "
        "{%0,%1,%2,%3}, {%4,%5}, {%6}, {%0,%1,%2,%3};"
        : "+f"(c[0]), "+f"(c[1]), "+f"(c[2]), "+f"(c[3])
        : "r"(a[0]), "r"(a[1]), "r"(b));
}
__device__ __forceinline__ void ldsm_x4(uint32_t* r, uint32_t addr) {
    asm volatile("ldmatrix.sync.aligned.m8n8.x4.shared.b16 {%0,%1,%2,%3}, [%4];"
        : "=r"(r[0]), "=r"(r[1]), "=r"(r[2]), "=r"(r[3]) : "r"(addr));
}
__device__ __forceinline__ void ldsm_x2(uint32_t* r, uint32_t addr) {
    asm volatile("ldmatrix.sync.aligned.m8n8.x2.shared.b16 {%0,%1}, [%2];"
        : "=r"(r[0]), "=r"(r[1]) : "r"(addr));
}
__device__ __forceinline__ void ldsm_x1(uint32_t* r, uint32_t addr) {
    asm volatile("ldmatrix.sync.aligned.m8n8.x1.shared.b16 {%0}, [%1];"
        : "=r"(r[0]) : "r"(addr));
}
__device__ __forceinline__ uint32_t s2u(const void* p) {
    return (uint32_t)__cvta_generic_to_shared(p);
}
__device__ __forceinline__ void cpa16(uint32_t s, const void* g) {
    asm volatile("cp.async.ca.shared.global [%0], [%1], 16;" :: "r"(s), "l"(g));
}
__device__ __forceinline__ uint32_t exp2_f16x2(float lo, float hi) {
    uint32_t c, e;
    asm("cvt.rn.f16x2.f32 %0, %1, %2;" : "=r"(c) : "f"(hi), "f"(lo));
    asm("ex2.approx.f16x2 %0, %1;" : "=r"(e) : "r"(c));
    return e;
}
#define CP_COMMIT() asm volatile("cp.async.commit_group;")
#define CP_WAIT0()  asm volatile("cp.async.wait_group 0;")
#define CP_WAIT1()  asm volatile("cp.async.wait_group 1;")

// ---------------------------------------------------------------------------
// Prep: fp32 -> fp16, 8 elems/thread.
// ---------------------------------------------------------------------------
__global__ __launch_bounds__(256)
void prep_cvt(const float* __restrict__ x, const float* __restrict__ wq,
              const float* __restrict__ wp) {
    const size_t i8 = ((size_t)blockIdx.x * 256 + threadIdx.x) * 8;
    const float* src; __half* dst; size_t off;
    if (i8 < SX)                  { src = x;  dst = g_xf;  off = i8; }
    else if (i8 < SX + SQW)       { src = wq; dst = g_wqf; off = i8 - SX; }
    else if (i8 < SX + SQW + SPW) { src = wp; dst = g_wpf; off = i8 - SX - SQW; }
    else return;
    const float4 v0 = *(const float4*)(src + off);
    const float4 v1 = *(const float4*)(src + off + 4);
    uint32_t r[4];
    r[0] = pack2h(__float2half_rn(v0.x), __float2half_rn(v0.y));
    r[1] = pack2h(__float2half_rn(v0.z), __float2half_rn(v0.w));
    r[2] = pack2h(__float2half_rn(v1.x), __float2half_rn(v1.y));
    r[3] = pack2h(__float2half_rn(v1.z), __float2half_rn(v1.w));
    *(uint4*)&dst[off] = *(uint4*)r;
}

// ---------------------------------------------------------------------------
// Aug fill: q: [fy/8, fx/8, -1/8, -M0, 0..]  k: [16w*fy, 16w*fx, 8w*kz, 1, 0..]
// ---------------------------------------------------------------------------
__global__ __launch_bounds__(256)
void aug_fill(const float* __restrict__ lw) {
    const int idx = blockIdx.x * 256 + threadIdx.x;
    if (idx >= BB * HH * NN) return;
    const int bh = idx / NN, n = idx - bh * NN;
    const int h = bh & 7;
    const int y = n / GG, x = n - y * GG;
    const float wb2 = lw[h] * (LOG2E / 4418.0f);
    const float fy = (float)y, fx = (float)x;

    uint32_t qa[4], ka[4];
    qa[0] = pack2h(__float2half_rn(fy * 0.125f), __float2half_rn(fx * 0.125f));
    qa[1] = pack2h(__float2half_rn(-0.125f), __float2half_rn(-M0));
    qa[2] = 0u; qa[3] = 0u;
    ka[0] = pack2h(__float2half_rn(16.0f * wb2 * fy), __float2half_rn(16.0f * wb2 * fx));
    ka[1] = pack2h(__float2half_rn(8.0f * wb2 * (fy * fy + fx * fx)), __float2half_rn(1.0f));
    ka[2] = 0u; ka[3] = 0u;

    *(uint4*)(g_qf + ((size_t)bh * NN + n) * DQ + 64) = *(uint4*)qa;
    *(uint4*)(g_kf + ((size_t)bh * NN + n) * DQ + 64) = *(uint4*)ka;
}

// ---------------------------------------------------------------------------
// GEMM fp16: block 128x128, k-chunk 32, 8 warps (2m x 4n), 3-stage pipe,
// one barrier per iteration.
// ---------------------------------------------------------------------------
constexpr int GSTR = 40;
constexpr int G_TILE = 128 * GSTR;
constexpr int G_STAGE = 2 * G_TILE;
constexpr int G_SMEM = 3 * G_STAGE * 2;

template <int MODE>
__global__ __launch_bounds__(256, 2)
void mma_gemm(const float* __restrict__ bias, const float* __restrict__ temp,
              float* __restrict__ out) {
    extern __shared__ __half smem[];

    const __half* A = (MODE == 0) ? g_xf : g_atf;
    const __half* B = (MODE == 0) ? g_wqf : g_wpf;

    const int tid = threadIdx.x;
    const int lane = tid & 31, warp = tid >> 5;
    const int wm = warp >> 2, wn = warp & 3;
    const int bm = blockIdx.x * 128, bn = blockIdx.y * 128;

    auto load_stage = [&](int s, int k0) {
        __half* base = smem + s * G_STAGE;
#pragma unroll
        for (int it = 0; it < 2; it++) {
            const int c = tid + 256 * it;
            const int row = c >> 2, col = c & 3;
            const size_t ga = (size_t)(bm + row) * CC + k0 + col * 8;
            const size_t gb = (size_t)(bn + row) * CC + k0 + col * 8;
            const int so = row * GSTR + col * 8;
            cpa16(s2u(base + so), &A[ga]);
            cpa16(s2u(base + G_TILE + so), &B[gb]);
        }
        CP_COMMIT();
    };

    float acc[4][4][4];
#pragma unroll
    for (int i = 0; i < 4; i++)
#pragma unroll
        for (int j = 0; j < 4; j++)
#pragma unroll
            for (int r = 0; r < 4; r++) acc[i][j][r] = 0.0f;

    constexpr int NIT = CC / 32;
    load_stage(0, 0);
    load_stage(1, 32);
    for (int i = 0; i < NIT; i++) {
        if (i + 1 < NIT) { CP_WAIT1(); } else { CP_WAIT0(); }
        __syncthreads();
        if (i + 2 < NIT) load_stage((i + 2) % 3, (i + 2) * 32);
        const __half* sA = smem + (i % 3) * G_STAGE;
        const __half* sB = sA + G_TILE;

        uint32_t bf[4][4];
#pragma unroll
        for (int nt = 0; nt < 4; nt++) {
            const int boff = (wn * 32 + nt * 8 + (lane & 7)) * GSTR + (lane >> 3) * 8;
            ldsm_x4(bf[nt], s2u(&sB[boff]));
        }
#pragma unroll
        for (int mt = 0; mt < 4; mt++) {
            uint32_t af[2][4];
#pragma unroll
            for (int s = 0; s < 2; s++) {
                const int aoff = (wm * 64 + mt * 16 + (lane & 15)) * GSTR + s * 16 + (lane >> 4) * 8;
                ldsm_x4(af[s], s2u(&sA[aoff]));
            }
#pragma unroll
            for (int s = 0; s < 2; s++)
#pragma unroll
                for (int nt = 0; nt < 4; nt++)
                    mma16816h(acc[mt][nt], af[s], &bf[nt][2 * s]);
        }
    }

#pragma unroll
    for (int mt = 0; mt < 4; mt++) {
#pragma unroll
        for (int nt = 0; nt < 4; nt++) {
            const int rA = bm + wm * 64 + mt * 16 + (lane >> 2);
            const int rB = rA + 8;
            const int o = bn + wn * 32 + nt * 8 + 2 * (lane & 3);
            if (MODE == 0) {
                const int part = o >> 9, h = (o >> 6) & 7, d = o & 63;
                const int bA = rA / NN, nA = rA - bA * NN;
                const int bB = rB / NN, nB = rB - bB * NN;
                const int bhA = bA * HH + h, bhB = bB * HH + h;
                float sc = 1.0f;
                if (part == 0) sc = __expf(temp[h]) * LOG2E;
                const __half f0 = __float2half_rn(acc[mt][nt][0] * sc);
                const __half f1 = __float2half_rn(acc[mt][nt][1] * sc);
                const __half f2 = __float2half_rn(acc[mt][nt][2] * sc);
                const __half f3 = __float2half_rn(acc[mt][nt][3] * sc);
                if (part == 2) {
                    const size_t iA = ((size_t)bhA * DD + d) * NN + nA;
                    const size_t iB = ((size_t)bhB * DD + d) * NN + nB;
                    g_vtf[iA] = f0; g_vtf[iA + NN] = f1;
                    g_vtf[iB] = f2; g_vtf[iB + NN] = f3;
                } else {
                    __half* dst = (part == 0) ? g_qf : g_kf;
                    const size_t iA = ((size_t)bhA * NN + nA) * DQ + d;
                    const size_t iB = ((size_t)bhB * NN + nB) * DQ + d;
                    *(uint32_t*)&dst[iA] = pack2h(f0, f1);
                    *(uint32_t*)&dst[iB] = pack2h(f2, f3);
                }
            } else {
                const float b0 = bias[o], b1 = bias[o + 1];
                *(float2*)&out[(size_t)rA * CC + o] =
                    make_float2(acc[mt][nt][0] + b0, acc[mt][nt][1] + b1);
                *(float2*)&out[(size_t)rB * CC + o] =
                    make_float2(acc[mt][nt][2] + b0, acc[mt][nt][3] + b1);
            }
        }
    }
}

// ---------------------------------------------------------------------------
// Flash attention, fp16, augmented D=72 QK^T, softmax fused into t-loop
// (small register lifetime -> 2 CTAs/SM). CTA = 128 q x one (b,h), 4 warps x 32q.
// ---------------------------------------------------------------------------
constexpr int QSTR = 88;
constexpr int VSTR = 72;
constexpr int FQ_ELE = 128 * QSTR;
constexpr int F_K_ELE = 64 * QSTR;
constexpr int F_V_ELE = 64 * VSTR;
constexpr int F_STAGE = F_K_ELE + F_V_ELE;
constexpr int F_SMEM = (FQ_ELE + 3 * F_STAGE) * 2;  // 83968 B

__global__ __launch_bounds__(128, 2)
void flash_mma() {
    extern __shared__ __half hmem[];
    __half* Qs  = hmem;
    __half* kvs = hmem + FQ_ELE;

    const int tid = threadIdx.x;
    const int lane = tid & 31, warp = tid >> 5;
    const int q0 = blockIdx.x * 128;
    const int bh = blockIdx.y;
    const int b = bh >> 3, h = bh & 7;

    const __half* Qg = g_qf + (size_t)bh * NN * DQ;
    const __half* Kg = g_kf + (size_t)bh * NN * DQ;
    const __half* Vg = g_vtf + (size_t)bh * NN * DD;  // [d][n]

    // ---- Stage Q (128 x 72) ----
#pragma unroll
    for (int it = 0; it < 8; it++) {
        const int c = tid + 128 * it;
        const int row = c >> 3, col = c & 7;
        cpa16(s2u(&Qs[row * QSTR + col * 8]), &Qg[(size_t)(q0 + row) * DQ + col * 8]);
    }
    cpa16(s2u(&Qs[tid * QSTR + 64]), &Qg[(size_t)(q0 + tid) * DQ + 64]);
    CP_COMMIT();
    CP_WAIT0();
    __syncthreads();

    uint32_t qf[2][4][4], qfa[2][2];
#pragma unroll
    for (int g = 0; g < 2; g++) {
#pragma unroll
        for (int s = 0; s < 4; s++) {
            const int off = (warp * 32 + g * 16 + (lane & 15)) * QSTR + s * 16 + (lane >> 4) * 8;
            ldsm_x4(qf[g][s], s2u(&Qs[off]));
        }
        const int offa = (warp * 32 + g * 16 + (lane & 15)) * QSTR + 64;
        ldsm_x2(qfa[g], s2u(&Qs[offa]));
    }

    auto load_kv = [&](int s, int k0) {
        __half* kb = kvs + s * F_STAGE;
        __half* vb = kb + F_K_ELE;
#pragma unroll
        for (int it = 0; it < 4; it++) {
            const int c = tid + 128 * it;
            const int row = c >> 3, col = c & 7;
            cpa16(s2u(&kb[row * QSTR + col * 8]), &Kg[(size_t)(k0 + row) * DQ + col * 8]);
            cpa16(s2u(&vb[row * VSTR + col * 8]), &Vg[(size_t)row * NN + k0 + col * 8]);
        }
        if (tid < 64) {
            cpa16(s2u(&kb[tid * QSTR + 64]), &Kg[(size_t)(k0 + tid) * DQ + 64]);
        }
        CP_COMMIT();
    };

    float oacc[2][8][4];
#pragma unroll
    for (int g = 0; g < 2; g++)
#pragma unroll
        for (int u = 0; u < 8; u++)
#pragma unroll
            for (int r = 0; r < 4; r++) oacc[g][u][r] = 0.0f;
    float lacc[2][4];
#pragma unroll
    for (int g = 0; g < 2; g++)
#pragma unroll
        for (int r = 0; r < 4; r++) lacc[g][r] = 0.0f;

    const uint32_t ONES2 = 0x3C003C00u;
    uint32_t onesb[2] = {ONES2, ONES2};

    constexpr int NKT = NN / 64;  // 36
    load_kv(0, 0);
    load_kv(1, 64);
    for (int kt = 0; kt < NKT; kt++) {
        if (kt + 1 < NKT) { CP_WAIT1(); } else { CP_WAIT0(); }
        __syncthreads();
        if (kt + 2 < NKT) load_kv((kt + 2) % 3, (kt + 2) * 64);
        const __half* sK = kvs + (kt % 3) * F_STAGE;
        const __half* sV = sK + F_K_ELE;

        // QK^T with fused exp2 -> P fragments (score regs live only per-t)
        uint32_t pf[2][4][4];
#pragma unroll
        for (int t = 0; t < 8; t++) {
            const int base = (8 * t + (lane & 7)) * QSTR + (lane >> 3) * 8;
            uint32_t k01[4], k23[4], k4[1];
            ldsm_x4(k01, s2u(&sK[base]));
            ldsm_x4(k23, s2u(&sK[base + 32]));
            ldsm_x1(k4,  s2u(&sK[(8 * t + (lane & 7)) * QSTR + 64]));
#pragma unroll
            for (int g = 0; g < 2; g++) {
                float sfr[4] = {0.0f, 0.0f, 0.0f, 0.0f};
                mma16816h(sfr, qf[g][0], &k01[0]);
                mma16816h(sfr, qf[g][1], &k01[2]);
                mma16816h(sfr, qf[g][2], &k23[0]);
                mma16816h(sfr, qf[g][3], &k23[2]);
                mma16808h(sfr, qfa[g], k4[0]);
                const int s = t >> 1, half = (t & 1) << 1;
                pf[g][s][half + 0] = exp2_f16x2(sfr[0], sfr[1]);
                pf[g][s][half + 1] = exp2_f16x2(sfr[2], sfr[3]);
            }
            if (t & 1) {   // pf[g][s] complete -> row-sum MMA
                const int s = t >> 1;
#pragma unroll
                for (int g = 0; g < 2; g++)
                    mma16816h(lacc[g], pf[g][s], onesb);
            }
        }

        // O += P @ V (V frags shared by both sub-tiles)
#pragma unroll
        for (int u = 0; u < 8; u++) {
            const int base = (8 * u + (lane & 7)) * VSTR + (lane >> 3) * 8;
            uint32_t v0f[4], v1f[4];
            ldsm_x4(v0f, s2u(&sV[base]));
            ldsm_x4(v1f, s2u(&sV[base + 32]));
#pragma unroll
            for (int g = 0; g < 2; g++) {
                mma16816h(oacc[g][u], pf[g][0], &v0f[0]);
                mma16816h(oacc[g][u], pf[g][1], &v0f[2]);
                mma16816h(oacc[g][u], pf[g][2], &v1f[0]);
                mma16816h(oacc[g][u], pf[g][3], &v1f[2]);
            }
        }
    }

    // epilogue: normalize by MMA row sums, write att fp16 [b][n][C]
#pragma unroll
    for (int g = 0; g < 2; g++) {
        const float invA = 1.0f / lacc[g][0], invB = 1.0f / lacc[g][2];
        const int qA = q0 + warp * 32 + g * 16 + (lane >> 2);
        const size_t baseA = ((size_t)(b * NN + qA)) * CC + h * DD;
        const size_t baseB = ((size_t)(b * NN + qA + 8)) * CC + h * DD;
#pragma unroll
        for (int u = 0; u < 8; u++) {
            const int c = 8 * u + 2 * (lane & 3);
            *(uint32_t*)&g_atf[baseA + c] =
                pack2h(__float2half_rn(oacc[g][u][0] * invA),
                       __float2half_rn(oacc[g][u][1] * invA));
            *(uint32_t*)&g_atf[baseB + c] =
                pack2h(__float2half_rn(oacc[g][u][2] * invB),
                       __float2half_rn(oacc[g][u][3] * invB));
        }
    }
}

// ---------------------------------------------------------------------------
extern "C" void kernel_launch(void* const* d_in, const int* in_sizes, int n_in,
                              void* d_out, int out_size) {
    const float* x      = (const float*)d_in[0];
    const float* qkv_w  = (const float*)d_in[1];
    const float* proj_w = (const float*)d_in[2];
    const float* proj_b = (const float*)d_in[3];
    const float* temp   = (const float*)d_in[4];
    const float* lw     = (const float*)d_in[5];
    float* out = (float*)d_out;

    cudaFuncSetAttribute(mma_gemm<0>, cudaFuncAttributeMaxDynamicSharedMemorySize, G_SMEM);
    cudaFuncSetAttribute(mma_gemm<1>, cudaFuncAttributeMaxDynamicSharedMemorySize, G_SMEM);
    cudaFuncSetAttribute(flash_mma,   cudaFuncAttributeMaxDynamicSharedMemorySize, F_SMEM);

    const int prep_blocks = (int)((SX + SQW + SPW) / 8 / 256);
    prep_cvt<<<prep_blocks, 256>>>(x, qkv_w, proj_w);

    mma_gemm<0><<<dim3(M_TOT / 128, 1536 / 128), 256, G_SMEM>>>(nullptr, temp, nullptr);

    aug_fill<<<(BB * HH * NN + 255) / 256, 256>>>(lw);

    flash_mma<<<dim3(NN / 128, BB * HH), 128, F_SMEM>>>();

    mma_gemm<1><<<dim3(M_TOT / 128, CC / 128), 256, G_SMEM>>>(proj_b, nullptr, out);
}